// round 16
// baseline (speedup 1.0000x reference)
#include <cuda_runtime.h>
#include <math.h>

// ---------------------------------------------------------------------------
// BatchShapingLoss, single fused kernel. 256 thr x 2 elems.
// Evaluation (validated rel_err 1.96e-7):
//   pcdf(z) = z^0.6 * Q(w) + A999 * (z/w)^0.6,  z = s-EPS, w = 1-z
//   Q fitted per octave of w (exponent-bit indexed), degree-9 Chebyshev.
// Rank: 2048-bin counting sort; after scatter, cnt[] IS the inclusive
//   prefix. Deterministic tie-break on original row.
// Finalize (new): TWO-LEVEL packed-atomic tree. 128 blocks -> 8 group
//   accumulators (16-deep chains in parallel) -> 1 root (8-deep). The
//   per-address L2 atomic serialization tail drops ~3.5k -> ~0.7k cyc.
//   Count lives in bits 56+, fixed-point 2^38 sum in bits 0..55; each
//   atomic's RETURN carries the complete sum when the count completes.
//   Self-resetting -> graph-replay safe; all-integer -> bit-deterministic.
// ---------------------------------------------------------------------------

#define EPSV  1e-10f
#define NOCT  32
#define NC    10
#define NB    2048
#define FXS   274877906944.0   // 2^38
#define CNT1  (1ULL << 56)
#define SUMM  0x00FFFFFFFFFFFFFFULL

struct Coefs {
    float ct[NC * NOCT];   // [j][octave], 320 floats
    float a999;
};

__device__ unsigned long long g_mid[8] = {0,0,0,0,0,0,0,0};
__device__ unsigned long long g_acc    = 0ULL;

static __device__ __forceinline__ float lg2f(float x) {
    float r; asm("lg2.approx.f32 %0, %1;" : "=f"(r) : "f"(x)); return r;
}
static __device__ __forceinline__ float ex2f(float x) {
    float r; asm("ex2.approx.f32 %0, %1;" : "=f"(r) : "f"(x)); return r;
}

static __device__ __forceinline__ float eval_pcdf(float v, const float* sc, float a999) {
    float z  = fmaxf(v - EPSV, 0.0f);
    float wv = 1.0f - z;
    unsigned int ui = __float_as_uint(wv);
    int iv = 126 - (int)(ui >> 23);
    iv = iv < 0 ? 0 : (iv > NOCT - 1 ? NOCT - 1 : iv);
    float t  = fmaf((float)(ui & 0x7fffffu), 0x1p-22f, -1.0f);
    float t2 = t + t;
    float b1 = 0.0f, b2 = 0.0f;
    #pragma unroll
    for (int j = NC - 1; j >= 1; j--) {
        float bb = fmaf(t2, b1, sc[j * NOCT + iv] - b2);
        b2 = b1; b1 = bb;
    }
    float Q  = fmaf(t, b1, sc[iv] - b2);
    float lz = lg2f(z);
    float lw = lg2f(wv);
    return fmaf(ex2f(0.6f * lz), Q, a999 * ex2f(0.6f * (lz - lw)));
}

__global__ void __launch_bounds__(256) fused_kernel(const float* __restrict__ x,
                                                    const Coefs cf,
                                                    float* __restrict__ out)
{
    __shared__ unsigned int cnt[NB];       // counts -> excl prefix -> incl prefix
    __shared__ float        sval[512];
    __shared__ unsigned int sidx[512];
    __shared__ float        sc[NC * NOCT];
    __shared__ float        wsum[8];
    __shared__ unsigned int woff[8];

    int tid = threadIdx.x;
    int c   = blockIdx.x;
    float v0 = __ldg(&x[tid * 128 + c]);
    float v1 = __ldg(&x[(tid + 256) * 128 + c]);

    if (tid < NC * NOCT / 4) ((uint4*)sc)[tid] = ((const uint4*)cf.ct)[tid];

    ((uint4*)cnt)[tid]       = make_uint4(0u, 0u, 0u, 0u);
    ((uint4*)cnt)[tid + 256] = make_uint4(0u, 0u, 0u, 0u);
    __syncthreads();                                            // B1

    int bin0 = (int)(v0 * (float)NB); bin0 = bin0 < 0 ? 0 : (bin0 > NB - 1 ? NB - 1 : bin0);
    int bin1 = (int)(v1 * (float)NB); bin1 = bin1 < 0 ? 0 : (bin1 > NB - 1 ? NB - 1 : bin1);
    atomicAdd(&cnt[bin0], 1u);
    atomicAdd(&cnt[bin1], 1u);
    __syncthreads();                                            // B2

    // ---- scan: 8 bins/thread ----
    uint4 a = ((uint4*)cnt)[2 * tid];
    uint4 b = ((uint4*)cnt)[2 * tid + 1];
    unsigned int e1 = a.x, e2 = e1 + a.y, e3 = e2 + a.z, e4 = e3 + a.w;
    unsigned int e5 = e4 + b.x, e6 = e5 + b.y, e7 = e6 + b.z;
    unsigned int tot = e7 + b.w;

    unsigned int incl = tot;
    #pragma unroll
    for (int o = 1; o < 32; o <<= 1) {
        unsigned int n = __shfl_up_sync(0xffffffffu, incl, o);
        if ((tid & 31) >= o) incl += n;
    }
    int wid = tid >> 5;
    if ((tid & 31) == 31) woff[wid] = incl;
    unsigned int wex = incl - tot;
    __syncthreads();                                            // B3

    uint4 wa = ((uint4*)woff)[0];
    uint4 wb = ((uint4*)woff)[1];
    unsigned int ws8[8] = {wa.x, wa.y, wa.z, wa.w, wb.x, wb.y, wb.z, wb.w};
    unsigned int base0 = wex;
    #pragma unroll
    for (int w = 0; w < 8; w++) base0 += (w < wid) ? ws8[w] : 0u;

    ((uint4*)cnt)[2 * tid]     = make_uint4(base0, base0 + e1, base0 + e2, base0 + e3);
    ((uint4*)cnt)[2 * tid + 1] = make_uint4(base0 + e4, base0 + e5, base0 + e6, base0 + e7);
    __syncthreads();                                            // B4

    unsigned int s0 = atomicAdd(&cnt[bin0], 1u);
    sval[s0] = v0; sidx[s0] = (unsigned int)tid;
    unsigned int s1 = atomicAdd(&cnt[bin1], 1u);
    sval[s1] = v1; sidx[s1] = (unsigned int)(tid + 256);
    __syncthreads();                                            // B5
    // cnt[b] is now the inclusive prefix

    // ---- ranks (deterministic: value, tie-break original row) ----
    unsigned int hi0 = cnt[bin0];
    unsigned int rb0 = bin0 ? cnt[bin0 - 1] : 0u;
    unsigned int rank0 = rb0;
    if (hi0 - rb0 > 1u)
        for (unsigned int j = rb0; j < hi0; j++) {
            float vj = sval[j]; unsigned int ij = sidx[j];
            rank0 += (vj < v0) || (vj == v0 && ij < (unsigned int)tid);
        }
    unsigned int hi1 = cnt[bin1];
    unsigned int rb1 = bin1 ? cnt[bin1 - 1] : 0u;
    unsigned int rank1 = rb1;
    if (hi1 - rb1 > 1u)
        for (unsigned int j = rb1; j < hi1; j++) {
            float vj = sval[j]; unsigned int ij = sidx[j];
            rank1 += (vj < v1) || (vj == v1 && ij < (unsigned int)(tid + 256));
        }

    // ---- evaluation (2x ILP) ----
    float p0f = eval_pcdf(v0, sc, cf.a999);
    float p1f = eval_pcdf(v1, sc, cf.a999);
    float d0  = p0f - (float)(rank0 + 1u) * (1.0f / 513.0f);
    float d1  = p1f - (float)(rank1 + 1u) * (1.0f / 513.0f);
    float sq  = fmaf(d0, d0, d1 * d1);

    // ---- block reduction ----
    #pragma unroll
    for (int o = 16; o > 0; o >>= 1) sq += __shfl_xor_sync(0xffffffffu, sq, o);
    if ((tid & 31) == 0) wsum[wid] = sq;
    __syncthreads();                                            // B6

    // ---- two-level packed-atomic tree finalize ----
    if (tid == 0) {
        float t = wsum[0] + wsum[1] + wsum[2] + wsum[3]
                + wsum[4] + wsum[5] + wsum[6] + wsum[7];
        unsigned long long fx =
            (unsigned long long)__double2ll_rn((double)t * FXS) + CNT1;
        int g = blockIdx.x >> 4;                        // 8 groups of 16 blocks
        unsigned long long gv = atomicAdd(&g_mid[g], fx) + fx;
        if ((gv >> 56) == 16ULL) {                      // group complete
            atomicExch(&g_mid[g], 0ULL);                // reset for next replay
            unsigned long long rv =
                atomicAdd(&g_acc, (gv & SUMM) + CNT1) + (gv & SUMM) + CNT1;
            if ((rv >> 56) == 8ULL) {                   // all groups in
                out[0] = (float)((double)(rv & SUMM)
                                 * (1.0 / FXS) * (1.0 / 512.0));
                atomicExch(&g_acc, 0ULL);               // reset for next replay
            }
        }
    }
}

extern "C" void kernel_launch(void* const* d_in, const int* in_sizes, int n_in,
                              void* d_out, int out_size) {
    const float* x = (const float*)d_in[0];

    double betaln = lgamma(0.6) + lgamma(0.4) - lgamma(1.0);
    double pref   = exp(-betaln) * pow(999.0, -0.6);
    const double PI = acos(-1.0);

    Coefs cf;
    cf.a999 = (float)(pref * 0.5 * pow(999.0, -0.4));

    static double ak[999];
    for (int k = 1; k <= 998; k++) {
        double wk = (k == 1) ? 0.5 : 1.0;
        ak[k] = pref * wk * pow((double)k, -0.4);
    }

    for (int ivv = 0; ivv < NOCT; ivv++) {
        int    e  = -1 - ivv;
        double s2 = ldexp(1.0, e);
        double wc = 1.5 * s2, wh = 0.5 * s2;
        double fv[NC];
        for (int i = 0; i < NC; i++) {
            double xi = cos(PI * (i + 0.5) / NC);
            double zz = 1.0 - (wc + wh * xi);
            double s  = 0.0;
            for (int k = 1; k <= 998; k++)
                s += ak[k] * pow(1.0 - (double)k * zz / 999.0, -0.6);
            fv[i] = s;
        }
        for (int j = 0; j < NC; j++) {
            double aa = 0.0;
            for (int i = 0; i < NC; i++)
                aa += fv[i] * cos(PI * j * (i + 0.5) / NC);
            aa *= 2.0 / NC;
            if (j == 0) aa *= 0.5;
            cf.ct[j * NOCT + ivv] = (float)aa;
        }
    }

    fused_kernel<<<128, 256>>>(x, cf, (float*)d_out);
}

// round 17
// speedup vs baseline: 1.2688x; 1.2688x over previous
#include <cuda_runtime.h>
#include <math.h>

// ---------------------------------------------------------------------------
// BatchShapingLoss, single fused kernel. 256 thr x 2 elems (best config).
// Evaluation (validated rel_err 1.96e-7):
//   pcdf(z) = z^0.6 * Q(w) + A999 * (z/w)^0.6,  z = s-EPS, w = 1-z
//   Q fitted per octave of w (exponent-bit indexed), degree-9 Chebyshev.
// Rank: 2048-bin counting sort; after scatter, cnt[] IS the inclusive
//   prefix. Deterministic tie-break on original row.
// Finalize: single packed u64 atomic (R15 form — the R16 two-level tree
//   REGRESSED and is reverted). Count in bits 56+, fixed-point 2^38 sum
//   in bits 0..55; the 128th block's atomic return carries the full sum.
// This round: eval chains issued BEFORE the rank loops so their ~150-cyc
//   FMA/MUFU latency overlaps the rank loops' LDS waits (pure reorder).
// ---------------------------------------------------------------------------

#define EPSV  1e-10f
#define NOCT  32
#define NC    10
#define NB    2048
#define FXS   274877906944.0   // 2^38

struct Coefs {
    float ct[NC * NOCT];   // [j][octave], 320 floats
    float a999;
};

__device__ unsigned long long g_acc = 0ULL;

static __device__ __forceinline__ float lg2f(float x) {
    float r; asm("lg2.approx.f32 %0, %1;" : "=f"(r) : "f"(x)); return r;
}
static __device__ __forceinline__ float ex2f(float x) {
    float r; asm("ex2.approx.f32 %0, %1;" : "=f"(r) : "f"(x)); return r;
}

static __device__ __forceinline__ float eval_pcdf(float v, const float* sc, float a999) {
    float z  = fmaxf(v - EPSV, 0.0f);
    float wv = 1.0f - z;
    unsigned int ui = __float_as_uint(wv);
    int iv = 126 - (int)(ui >> 23);
    iv = iv < 0 ? 0 : (iv > NOCT - 1 ? NOCT - 1 : iv);
    float t  = fmaf((float)(ui & 0x7fffffu), 0x1p-22f, -1.0f);
    float t2 = t + t;
    float b1 = 0.0f, b2 = 0.0f;
    #pragma unroll
    for (int j = NC - 1; j >= 1; j--) {
        float bb = fmaf(t2, b1, sc[j * NOCT + iv] - b2);
        b2 = b1; b1 = bb;
    }
    float Q  = fmaf(t, b1, sc[iv] - b2);
    float lz = lg2f(z);
    float lw = lg2f(wv);
    return fmaf(ex2f(0.6f * lz), Q, a999 * ex2f(0.6f * (lz - lw)));
}

__global__ void __launch_bounds__(256) fused_kernel(const float* __restrict__ x,
                                                    const Coefs cf,
                                                    float* __restrict__ out)
{
    __shared__ unsigned int cnt[NB];       // counts -> excl prefix -> incl prefix
    __shared__ float        sval[512];
    __shared__ unsigned int sidx[512];
    __shared__ float        sc[NC * NOCT];
    __shared__ float        wsum[8];
    __shared__ unsigned int woff[8];

    int tid = threadIdx.x;
    int c   = blockIdx.x;
    float v0 = __ldg(&x[tid * 128 + c]);
    float v1 = __ldg(&x[(tid + 256) * 128 + c]);

    // stage coefficients (80 uint4 = 320 floats) while loads are in flight
    if (tid < NC * NOCT / 4) ((uint4*)sc)[tid] = ((const uint4*)cf.ct)[tid];

    ((uint4*)cnt)[tid]       = make_uint4(0u, 0u, 0u, 0u);
    ((uint4*)cnt)[tid + 256] = make_uint4(0u, 0u, 0u, 0u);
    __syncthreads();                                            // B1

    int bin0 = (int)(v0 * (float)NB); bin0 = bin0 < 0 ? 0 : (bin0 > NB - 1 ? NB - 1 : bin0);
    int bin1 = (int)(v1 * (float)NB); bin1 = bin1 < 0 ? 0 : (bin1 > NB - 1 ? NB - 1 : bin1);
    atomicAdd(&cnt[bin0], 1u);
    atomicAdd(&cnt[bin1], 1u);
    __syncthreads();                                            // B2

    // ---- scan: 8 bins/thread ----
    uint4 a = ((uint4*)cnt)[2 * tid];
    uint4 b = ((uint4*)cnt)[2 * tid + 1];
    unsigned int e1 = a.x, e2 = e1 + a.y, e3 = e2 + a.z, e4 = e3 + a.w;
    unsigned int e5 = e4 + b.x, e6 = e5 + b.y, e7 = e6 + b.z;
    unsigned int tot = e7 + b.w;

    unsigned int incl = tot;
    #pragma unroll
    for (int o = 1; o < 32; o <<= 1) {
        unsigned int n = __shfl_up_sync(0xffffffffu, incl, o);
        if ((tid & 31) >= o) incl += n;
    }
    int wid = tid >> 5;
    if ((tid & 31) == 31) woff[wid] = incl;
    unsigned int wex = incl - tot;
    __syncthreads();                                            // B3

    uint4 wa = ((uint4*)woff)[0];
    uint4 wb = ((uint4*)woff)[1];
    unsigned int ws8[8] = {wa.x, wa.y, wa.z, wa.w, wb.x, wb.y, wb.z, wb.w};
    unsigned int base0 = wex;
    #pragma unroll
    for (int w = 0; w < 8; w++) base0 += (w < wid) ? ws8[w] : 0u;

    // write exclusive prefixes back into cnt (scatter turns them inclusive)
    ((uint4*)cnt)[2 * tid]     = make_uint4(base0, base0 + e1, base0 + e2, base0 + e3);
    ((uint4*)cnt)[2 * tid + 1] = make_uint4(base0 + e4, base0 + e5, base0 + e6, base0 + e7);
    __syncthreads();                                            // B4

    unsigned int s0 = atomicAdd(&cnt[bin0], 1u);
    sval[s0] = v0; sidx[s0] = (unsigned int)tid;
    unsigned int s1 = atomicAdd(&cnt[bin1], 1u);
    sval[s1] = v1; sidx[s1] = (unsigned int)(tid + 256);
    __syncthreads();                                            // B5
    // cnt[b] is now the inclusive prefix

    // ---- evaluation FIRST: long independent FMA/MUFU chains issue while
    //      the rank loops below wait on LDS ----
    float p0f = eval_pcdf(v0, sc, cf.a999);
    float p1f = eval_pcdf(v1, sc, cf.a999);

    // ---- ranks (deterministic: value, tie-break original row) ----
    unsigned int hi0 = cnt[bin0];
    unsigned int rb0 = bin0 ? cnt[bin0 - 1] : 0u;
    unsigned int rank0 = rb0;
    if (hi0 - rb0 > 1u)
        for (unsigned int j = rb0; j < hi0; j++) {
            float vj = sval[j]; unsigned int ij = sidx[j];
            rank0 += (vj < v0) || (vj == v0 && ij < (unsigned int)tid);
        }
    unsigned int hi1 = cnt[bin1];
    unsigned int rb1 = bin1 ? cnt[bin1 - 1] : 0u;
    unsigned int rank1 = rb1;
    if (hi1 - rb1 > 1u)
        for (unsigned int j = rb1; j < hi1; j++) {
            float vj = sval[j]; unsigned int ij = sidx[j];
            rank1 += (vj < v1) || (vj == v1 && ij < (unsigned int)(tid + 256));
        }

    float d0  = p0f - (float)(rank0 + 1u) * (1.0f / 513.0f);
    float d1  = p1f - (float)(rank1 + 1u) * (1.0f / 513.0f);
    float sq  = fmaf(d0, d0, d1 * d1);

    // ---- reduction + packed single-atomic finalize (R15 form) ----
    #pragma unroll
    for (int o = 16; o > 0; o >>= 1) sq += __shfl_xor_sync(0xffffffffu, sq, o);
    if ((tid & 31) == 0) wsum[wid] = sq;
    __syncthreads();                                            // B6
    if (tid == 0) {
        float t = wsum[0] + wsum[1] + wsum[2] + wsum[3]
                + wsum[4] + wsum[5] + wsum[6] + wsum[7];
        unsigned long long fx =
            (unsigned long long)__double2ll_rn((double)t * FXS)
            + (1ULL << 56);
        unsigned long long newv = atomicAdd(&g_acc, fx) + fx;
        if ((newv >> 56) == 128ULL) {          // last block: newv has full sum
            out[0] = (float)((double)(newv & 0x00FFFFFFFFFFFFFFULL)
                             * (1.0 / FXS) * (1.0 / 512.0));
            atomicExch(&g_acc, 0ULL);          // reset for next graph replay
        }
    }
}

extern "C" void kernel_launch(void* const* d_in, const int* in_sizes, int n_in,
                              void* d_out, int out_size) {
    const float* x = (const float*)d_in[0];

    double betaln = lgamma(0.6) + lgamma(0.4) - lgamma(1.0);
    double pref   = exp(-betaln) * pow(999.0, -0.6);
    const double PI = acos(-1.0);

    Coefs cf;
    cf.a999 = (float)(pref * 0.5 * pow(999.0, -0.4));

    static double ak[999];
    for (int k = 1; k <= 998; k++) {
        double wk = (k == 1) ? 0.5 : 1.0;
        ak[k] = pref * wk * pow((double)k, -0.4);
    }

    for (int ivv = 0; ivv < NOCT; ivv++) {
        int    e  = -1 - ivv;
        double s2 = ldexp(1.0, e);
        double wc = 1.5 * s2, wh = 0.5 * s2;
        double fv[NC];
        for (int i = 0; i < NC; i++) {
            double xi = cos(PI * (i + 0.5) / NC);
            double zz = 1.0 - (wc + wh * xi);
            double s  = 0.0;
            for (int k = 1; k <= 998; k++)
                s += ak[k] * pow(1.0 - (double)k * zz / 999.0, -0.6);
            fv[i] = s;
        }
        for (int j = 0; j < NC; j++) {
            double aa = 0.0;
            for (int i = 0; i < NC; i++)
                aa += fv[i] * cos(PI * j * (i + 0.5) / NC);
            aa *= 2.0 / NC;
            if (j == 0) aa *= 0.5;
            cf.ct[j * NOCT + ivv] = (float)aa;
        }
    }

    fused_kernel<<<128, 256>>>(x, cf, (float*)d_out);
}